// round 14
// baseline (speedup 1.0000x reference)
#include <cuda_runtime.h>
#include <cuda_pipeline.h>
#include <cuda_fp16.h>
#include <mma.h>
#include <cstdint>

using namespace nvcuda;

namespace {
constexpr int BATCH = 8;
constexpr int CH    = 1024;
constexpr int P     = 48 * 48;     // 2304
constexpr int PD    = 24;
constexpr int PI    = PD * PD;     // 576
constexpr int S     = PI * PI;     // 331776
constexpr float EPS_L2 = 1e-6f;
constexpr float EPS_MM = 1e-5f;
}

__device__ float  g_inva[BATCH * P];
__device__ float  g_invb[BATCH * P];
__device__ __half g_fah[(size_t)BATCH * CH * P];  // scaled fp16 A, [b][k][p]
__device__ __half g_fbh[(size_t)BATCH * CH * P];  // scaled fp16 B, [b][k][p]
__device__ float  g_pool[(size_t)BATCH * S];
__device__ float  g_x0  [(size_t)BATCH * S];
__device__ float  g_y1  [(size_t)BATCH * 10 * S];
__device__ float  g_y2  [(size_t)BATCH * 10 * S];
__device__ float  g_y3  [(size_t)BATCH * S];
__device__ float  g_rmax[BATCH * PI];
__device__ float  g_cmax[BATCH * PI];

// ---------------- f32x2 packed helpers (convs) ----------------
__device__ __forceinline__ void fma2(unsigned long long& d, unsigned long long a,
                                     unsigned long long b) {
    asm("fma.rn.f32x2 %0, %1, %2, %0;" : "+l"(d) : "l"(a), "l"(b));
}
__device__ __forceinline__ unsigned long long pack2(float lo, float hi) {
    unsigned long long r;
    asm("mov.b64 %0, {%1, %2};" : "=l"(r) : "f"(lo), "f"(hi));
    return r;
}
__device__ __forceinline__ void unpack2(unsigned long long v, float& lo, float& hi) {
    asm("mov.b64 {%0, %1}, %2;" : "=f"(lo), "=f"(hi) : "l"(v));
}

// ---------------- per-position inverse L2 norms ----------------
__global__ void norm_kernel(const float* __restrict__ fa, const float* __restrict__ fb) {
    int idx = blockIdx.x * blockDim.x + threadIdx.x;
    int b = idx / P, p = idx - b * P;
    const float* a  = fa + (size_t)b * CH * P + p;
    const float* bb = fb + (size_t)b * CH * P + p;
    float sa = 0.f, sb = 0.f;
#pragma unroll 8
    for (int c = 0; c < CH; c++) {
        float x = a[(size_t)c * P];  sa = fmaf(x, x, sa);
        float y = bb[(size_t)c * P]; sb = fmaf(y, y, sb);
    }
    g_inva[idx] = rsqrtf(sa + EPS_L2);
    g_invb[idx] = rsqrtf(sb + EPS_L2);
}

__global__ void zero_pool_kernel() {
    size_t i = (size_t)blockIdx.x * blockDim.x + threadIdx.x;
    g_pool[i] = 0.f;
    if (i < BATCH * PI) g_cmax[i] = 0.f;
}
__global__ void zero_cmax_kernel() {
    int i = blockIdx.x * blockDim.x + threadIdx.x;
    if (i < BATCH * PI) g_cmax[i] = 0.f;
}

// ---- scale-by-invnorm + fp16 convert, layout preserved [b][k][p] ----
__global__ void scale_half_kernel(const float* __restrict__ fa,
                                  const float* __restrict__ fb) {
    size_t i4 = (size_t)blockIdx.x * blockDim.x + threadIdx.x;   // 4 elements each
    size_t i  = i4 * 4;
    if (i >= (size_t)BATCH * CH * P) return;
    int b  = (int)(i / ((size_t)CH * P));
    int p  = (int)(i % P);
    const float4 a4 = *reinterpret_cast<const float4*>(fa + i);
    const float4 b4 = *reinterpret_cast<const float4*>(fb + i);
    const float* ia = g_inva + b * P + p;
    const float* ib = g_invb + b * P + p;
    __half2 ha0 = __floats2half2_rn(a4.x * ia[0], a4.y * ia[1]);
    __half2 ha1 = __floats2half2_rn(a4.z * ia[2], a4.w * ia[3]);
    __half2 hb0 = __floats2half2_rn(b4.x * ib[0], b4.y * ib[1]);
    __half2 hb1 = __floats2half2_rn(b4.z * ib[2], b4.w * ib[3]);
    *reinterpret_cast<__half2*>(&g_fah[i])     = ha0;
    *reinterpret_cast<__half2*>(&g_fah[i + 2]) = ha1;
    *reinterpret_cast<__half2*>(&g_fbh[i])     = hb0;
    *reinterpret_cast<__half2*>(&g_fbh[i + 2]) = hb1;
}

// ---- correlation GEMM: fp16 wmma, fp16 ACC, BM=128 BN=256, 64x64 warps ----
// Frozen at R13 winner (470us, regs 126, no spills).
__global__ void __launch_bounds__(256, 2)
corr_kernel(const __half* __restrict__ fah, const __half* __restrict__ fbh) {
    extern __shared__ __align__(16) char sm[];
    __half* Asm = reinterpret_cast<__half*>(sm);            // [2][32][136]
    __half* Bsm = reinterpret_cast<__half*>(sm + 17408);    // [2][32][264]
    __half* wb  = reinterpret_cast<__half*>(sm + 17408 + 33792);  // [8][256]

    const int b  = blockIdx.z;
    const __half* Ag = fah + (size_t)b * CH * P;
    const __half* Bg = fbh + (size_t)b * CH * P;
    const int m0 = blockIdx.x * 128, n0 = blockIdx.y * 256;
    const int tid = threadIdx.x, wid = tid >> 5, lane = tid & 31;
    const int wm = wid & 1, wn = wid >> 1;   // warp tile 64(m) x 64(n)

    wmma::fragment<wmma::accumulator, 16, 16, 16, __half> acc[4][4];
#pragma unroll
    for (int i = 0; i < 4; i++)
#pragma unroll
        for (int j = 0; j < 4; j++) wmma::fill_fragment(acc[i][j], __float2half(0.f));

    auto As = [&](int buf, int r, int c) -> __half* { return Asm + (buf * 32 + r) * 136 + c; };
    auto Bs = [&](int buf, int r, int c) -> __half* { return Bsm + (buf * 32 + r) * 264 + c; };

    auto load_tile = [&](int kt, int buf) {
        const int k0 = kt * 32;
#pragma unroll
        for (int v = 0; v < 2; v++) {              // A: 128 wide
            int l = v * 256 + tid;
            int r = l >> 4, c = (l & 15) * 8;
            __pipeline_memcpy_async(As(buf, r, c), Ag + (size_t)(k0 + r) * P + m0 + c, 16);
        }
#pragma unroll
        for (int v = 0; v < 4; v++) {              // B: 256 wide
            int l = v * 256 + tid;
            int r = l >> 5, c = (l & 31) * 8;
            __pipeline_memcpy_async(Bs(buf, r, c), Bg + (size_t)(k0 + r) * P + n0 + c, 16);
        }
        __pipeline_commit();
    };

    load_tile(0, 0);
    const int NT = CH / 32;   // 32
    for (int kt = 0; kt < NT; kt++) {
        if (kt + 1 < NT) load_tile(kt + 1, (kt + 1) & 1);
        __pipeline_wait_prior((kt + 1 < NT) ? 1 : 0);
        __syncthreads();
        const int buf = kt & 1;
#pragma unroll
        for (int ks = 0; ks < 2; ks++) {
            const int kk = ks * 16;
            wmma::fragment<wmma::matrix_a, 16, 16, 16, __half, wmma::col_major> af[4];
#pragma unroll
            for (int i = 0; i < 4; i++)
                wmma::load_matrix_sync(af[i], As(buf, kk, wm * 64 + i * 16), 136);
#pragma unroll
            for (int j = 0; j < 4; j++) {
                wmma::fragment<wmma::matrix_b, 16, 16, 16, __half, wmma::row_major> bf;
                wmma::load_matrix_sync(bf, Bs(buf, kk, wn * 64 + j * 16), 264);
#pragma unroll
                for (int i = 0; i < 4; i++)
                    wmma::mma_sync(acc[i][j], af[i], bf, acc[i][j]);
            }
        }
        __syncthreads();
    }

    __half* wbuf = wb + wid * 256;
#pragma unroll 1
    for (int i = 0; i < 4; i++) {
#pragma unroll 1
        for (int j = 0; j < 4; j++) {
            wmma::store_matrix_sync(wbuf, acc[i][j], 16, wmma::mem_row_major);
            __syncwarp();
            const int tm0 = m0 + wm * 64 + i * 16;
            const int tn0 = n0 + wn * 64 + j * 16;
            const int row = lane >> 1;
            const int cb  = (lane & 1) * 8;
            const int p   = tm0 + row;
            float v[8];
#pragma unroll
            for (int c = 0; c < 8; c++) v[c] = __half2float(wbuf[row * 16 + cb + c]);
            float c2[4];
#pragma unroll
            for (int u = 0; u < 4; u++) c2[u] = fmaxf(v[2 * u], v[2 * u + 1]);
#pragma unroll
            for (int u = 0; u < 4; u++)
                c2[u] = fmaxf(c2[u], __shfl_xor_sync(0xffffffffu, c2[u], 2));
            if ((lane & 2) == 0) {
                const int PA = ((p / 48) >> 1) * 24 + ((p % 48) >> 1);
                float* poolb = g_pool + (size_t)b * S + (size_t)PA * PI;
#pragma unroll
                for (int u = 0; u < 4; u++) {
                    int q  = tn0 + cb + 2 * u;
                    int PB = ((q / 48) >> 1) * 24 + ((q % 48) >> 1);
                    atomicMax(reinterpret_cast<int*>(&poolb[PB]), __float_as_int(c2[u]));
                }
            }
            __syncwarp();
        }
    }
}

// ---------------- mutual matching ----------------
__global__ void rowmax_kernel(int which) {
    const float* x = (which == 0) ? g_pool : g_y3;
    int row  = blockIdx.x * 8 + (threadIdx.x >> 5);
    int lane = threadIdx.x & 31;
    const float* xr = x + (size_t)row * PI;
    float m = 0.f;
    for (int j = lane; j < PI; j += 32) m = fmaxf(m, xr[j]);
#pragma unroll
    for (int o = 16; o; o >>= 1) m = fmaxf(m, __shfl_xor_sync(0xffffffffu, m, o));
    if (lane == 0) g_rmax[row] = m;
}

__global__ void colmax_kernel(int which) {  // grid (8,16), 576 thr
    const float* x = (which == 0) ? g_pool : g_y3;
    int b = blockIdx.x, j = threadIdx.x;
    const float* xb = x + (size_t)b * S;
    int i0 = blockIdx.y * 36;
    float m = 0.f;
    for (int i = i0; i < i0 + 36; i++) m = fmaxf(m, xb[(size_t)i * PI + j]);
    atomicMax(reinterpret_cast<int*>(&g_cmax[b * PI + j]), __float_as_int(m));
}

__global__ void mm_apply_kernel(int which, float* __restrict__ outp) {
    int idx = blockIdx.x * blockDim.x + threadIdx.x;
    int b = idx / S, rem = idx - b * S;
    int i = rem / PI, j = rem - i * PI;
    float v  = which ? g_y3[idx] : g_pool[idx];
    float rm = g_rmax[b * PI + i];
    float cm = g_cmax[b * PI + j];
    if (which == 0) {  // deferred x/sqrt(x^2+eps); monotone so maxes transform too
        v  = v  * rsqrtf(v  * v  + EPS_L2);
        rm = rm * rsqrtf(rm * rm + EPS_L2);
        cm = cm * rsqrtf(cm * cm + EPS_L2);
    }
    float* dst = which ? outp : g_x0;
    dst[idx] = v * (v / (rm + EPS_MM)) * (v / (cm + EPS_MM));
}

// ---- Conv4d 3^4 SAME: f32x2 FMA, 6 outputs/thread, batched 3-row loads ----
// Loop order (t1,t2,ci,t3): all 3 e3 rows load together (15 LDG in flight vs 5)
// to hide L2 latency. Edge rows are zero-filled (0*w adds exactly 0).
template <int CI, int CO>
__global__ void __launch_bounds__(256, 2)
conv_kernel(const float* __restrict__ x, float* __restrict__ y,
            const float* __restrict__ w, const float* __restrict__ bias) {
    extern __shared__ __align__(16) char dsm[];
    float2* ws2 = reinterpret_cast<float2*>(dsm);  // duplicated weight pairs
    __shared__ float bs[CO];
    for (int l = threadIdx.x; l < 81 * CI * CO; l += 256) {
        int tap = l / (CI * CO), r = l - tap * (CI * CO);
        int ci = r / CO, co = r - ci * CO;
        float wv = w[(co * CI + ci) * 81 + tap];
        ws2[l] = make_float2(wv, wv);
    }
    if (threadIdx.x < CO) bs[threadIdx.x] = bias[threadIdx.x];
    __syncthreads();

    int g = blockIdx.x * 256 + threadIdx.x;           // [0, BATCH*S/6)
    int b = g / (S / 6), r = g - b * (S / 6);
    int d4b = (r & 3) * 6; int r2 = r >> 2;
    int d3 = r2 % 24; r2 /= 24;
    int d2 = r2 % 24; int d1 = r2 / 24;
    int s0 = ((d1 * 24 + d2) * 24 + d3) * 24 + d4b;
    const bool leftEdge = (d4b == 0), rightEdge = (d4b == 18);
    const float* xb = x + (size_t)b * CI * S;

    unsigned long long acc[3][CO];
#pragma unroll
    for (int h = 0; h < 3; h++)
#pragma unroll
        for (int co = 0; co < CO; co++) acc[h][co] = 0ull;

#pragma unroll 1
    for (int t1 = 0; t1 < 3; t1++) {
        int e1 = d1 + t1 - 1; if ((unsigned)e1 >= 24u) continue;
#pragma unroll 1
        for (int t2 = 0; t2 < 3; t2++) {
            int e2 = d2 + t2 - 1; if ((unsigned)e2 >= 24u) continue;
            int plane = (e1 * 24 + e2) * 24;
            int tap2  = (t1 * 3 + t2) * 9;
#pragma unroll
            for (int ci = 0; ci < CI; ci++) {
                const float* xc = xb + (size_t)ci * S;
                float rw[3][8];   // [t3 row][w0..w7]
#pragma unroll
                for (int rr = 0; rr < 3; rr++) {
                    int e3 = d3 + rr - 1;
                    bool valid = (unsigned)e3 < 24u;
                    const float* xr = xc + (plane + (valid ? e3 : 0)) * 24 + d4b;
                    const float2* xp = reinterpret_cast<const float2*>(xr);
                    float2 a0 = valid ? xp[0] : make_float2(0.f, 0.f);
                    float2 a1 = valid ? xp[1] : make_float2(0.f, 0.f);
                    float2 a2 = valid ? xp[2] : make_float2(0.f, 0.f);
                    rw[rr][0] = (valid && !leftEdge)  ? xr[-1] : 0.f;
                    rw[rr][7] = (valid && !rightEdge) ? xr[6]  : 0.f;
                    rw[rr][1] = a0.x; rw[rr][2] = a0.y;
                    rw[rr][3] = a1.x; rw[rr][4] = a1.y;
                    rw[rr][5] = a2.x; rw[rr][6] = a2.y;
                }
#pragma unroll
                for (int t3 = 0; t3 < 3; t3++) {
                    const float* q = rw[t3];
                    unsigned long long E0 = pack2(q[0], q[1]);
                    unsigned long long E1 = pack2(q[2], q[3]);
                    unsigned long long E2 = pack2(q[4], q[5]);
                    unsigned long long E3 = pack2(q[6], q[7]);
                    unsigned long long O0 = pack2(q[1], q[2]);
                    unsigned long long O1 = pack2(q[3], q[4]);
                    unsigned long long O2 = pack2(q[5], q[6]);
                    const unsigned long long T[3][3] = {
                        {E0, E1, E2}, {O0, O1, O2}, {E1, E2, E3} };
#pragma unroll
                    for (int t4 = 0; t4 < 3; t4++) {
                        const unsigned long long A = T[t4][0], Bp = T[t4][1], Cp = T[t4][2];
                        const float2* wrow = ws2 + (((tap2 + t3 * 3) + t4) * CI + ci) * CO;
                        if (CO % 2 == 0) {
                            const ulonglong2* wq2 = reinterpret_cast<const ulonglong2*>(wrow);
#pragma unroll
                            for (int c2 = 0; c2 < CO / 2; c2++) {
                                ulonglong2 wv = wq2[c2];
                                fma2(acc[0][2 * c2],     A,  wv.x);
                                fma2(acc[1][2 * c2],     Bp, wv.x);
                                fma2(acc[2][2 * c2],     Cp, wv.x);
                                fma2(acc[0][2 * c2 + 1], A,  wv.y);
                                fma2(acc[1][2 * c2 + 1], Bp, wv.y);
                                fma2(acc[2][2 * c2 + 1], Cp, wv.y);
                            }
                        } else {
                            const unsigned long long* wq =
                                reinterpret_cast<const unsigned long long*>(wrow);
#pragma unroll
                            for (int co = 0; co < CO; co++) {
                                unsigned long long wv = wq[co];
                                fma2(acc[0][co], A,  wv);
                                fma2(acc[1][co], Bp, wv);
                                fma2(acc[2][co], Cp, wv);
                            }
                        }
                    }
                }
            }
        }
    }
#pragma unroll
    for (int co = 0; co < CO; co++) {
        float bb = bs[co];
        float* yo = &y[((size_t)b * CO + co) * S + s0];
#pragma unroll
        for (int h = 0; h < 3; h++) {
            float a0, a1;
            unpack2(acc[h][co], a0, a1);
            float2 o = make_float2(fmaxf(a0 + bb, 0.f), fmaxf(a1 + bb, 0.f));
            *reinterpret_cast<float2*>(yo + 2 * h) = o;
        }
    }
}

// ---- conv3 specialized (CI=10, CO=1): 18 outputs/thread (3 d3 x 6 d4) ----
__global__ void __launch_bounds__(256)
conv3_kernel(const float* __restrict__ x, float* __restrict__ y,
             const float* __restrict__ w, const float* __restrict__ bias) {
    __shared__ unsigned long long ws2[810];   // duplicated weight pairs [tap*10+ci]
    __shared__ float bs0;
    for (int l = threadIdx.x; l < 810; l += 256) {
        int tap = l / 10, ci = l - tap * 10;
        float wv = w[ci * 81 + tap];
        ws2[l] = pack2(wv, wv);
    }
    if (threadIdx.x == 0) bs0 = bias[0];
    __syncthreads();

    int g = blockIdx.x * 256 + threadIdx.x;   // [0, BATCH*S/18)
    int b = g / (S / 18), r = g - b * (S / 18);
    int d4b = (r & 3) * 6; int r2 = r >> 2;
    int d3s = (r2 & 7) * 3; r2 >>= 3;
    int d2 = r2 % 24; int d1 = r2 / 24;
    const bool leftEdge = (d4b == 0), rightEdge = (d4b == 18);
    const float* xb = x + (size_t)b * 10 * S;

    unsigned long long acc[3][3];
#pragma unroll
    for (int o = 0; o < 3; o++)
#pragma unroll
        for (int h = 0; h < 3; h++) acc[o][h] = 0ull;

#pragma unroll 1
    for (int t1 = 0; t1 < 3; t1++) {
        int e1 = d1 + t1 - 1; if ((unsigned)e1 >= 24u) continue;
#pragma unroll 1
        for (int t2 = 0; t2 < 3; t2++) {
            int e2 = d2 + t2 - 1; if ((unsigned)e2 >= 24u) continue;
            int plane = (e1 * 24 + e2) * 24;
            int tap2  = (t1 * 3 + t2) * 9;
#pragma unroll 1
            for (int ci = 0; ci < 10; ci++) {
                const float* xc = xb + (size_t)ci * S;
#pragma unroll
                for (int j = 0; j < 5; j++) {
                    int e3 = d3s - 1 + j;
                    if ((unsigned)e3 >= 24u) continue;
                    const float* xr = xc + (plane + e3) * 24 + d4b;
                    const float2* xp = reinterpret_cast<const float2*>(xr);
                    float2 m0 = xp[0], m1 = xp[1], m2 = xp[2];
                    float wL = leftEdge  ? 0.f : xr[-1];
                    float wR = rightEdge ? 0.f : xr[6];
                    unsigned long long E0 = pack2(wL,   m0.x);
                    unsigned long long E1 = pack2(m0.y, m1.x);
                    unsigned long long E2 = pack2(m1.y, m2.x);
                    unsigned long long E3 = pack2(m2.y, wR);
                    unsigned long long O0 = pack2(m0.x, m0.y);
                    unsigned long long O1 = pack2(m1.x, m1.y);
                    unsigned long long O2 = pack2(m2.x, m2.y);
                    const unsigned long long T[3][3] = {
                        {E0, E1, E2}, {O0, O1, O2}, {E1, E2, E3} };
#pragma unroll
                    for (int t3 = 0; t3 < 3; t3++) {
                        int o = j - t3;
                        if ((unsigned)o >= 3u) continue;
                        const unsigned long long* wq = &ws2[(tap2 + t3 * 3) * 10 + ci];
#pragma unroll
                        for (int t4 = 0; t4 < 3; t4++) {
                            unsigned long long wv = wq[t4 * 10];
                            fma2(acc[o][0], T[t4][0], wv);
                            fma2(acc[o][1], T[t4][1], wv);
                            fma2(acc[o][2], T[t4][2], wv);
                        }
                    }
                }
            }
        }
    }
    float bb = bs0;
#pragma unroll
    for (int o = 0; o < 3; o++) {
        float* yo = &y[(size_t)b * S + ((d1 * 24 + d2) * 24 + d3s + o) * 24 + d4b];
#pragma unroll
        for (int h = 0; h < 3; h++) {
            float a0, a1;
            unpack2(acc[o][h], a0, a1);
            *reinterpret_cast<float2*>(yo + 2 * h) =
                make_float2(fmaxf(a0 + bb, 0.f), fmaxf(a1 + bb, 0.f));
        }
    }
}

extern "C" void kernel_launch(void* const* d_in, const int* in_sizes, int n_in,
                              void* d_out, int out_size) {
    const float* fa = (const float*)d_in[0];
    const float* fb = (const float*)d_in[1];
    const float* w1 = (const float*)d_in[2];
    const float* b1 = (const float*)d_in[3];
    const float* w2 = (const float*)d_in[4];
    const float* b2 = (const float*)d_in[5];
    const float* w3 = (const float*)d_in[6];
    const float* b3 = (const float*)d_in[7];
    float* out = (float*)d_out;

    float *p_x0, *p_y1, *p_y2, *p_y3;
    __half *p_fah, *p_fbh;
    cudaGetSymbolAddress((void**)&p_x0, g_x0);
    cudaGetSymbolAddress((void**)&p_y1, g_y1);
    cudaGetSymbolAddress((void**)&p_y2, g_y2);
    cudaGetSymbolAddress((void**)&p_y3, g_y3);
    cudaGetSymbolAddress((void**)&p_fah, g_fah);
    cudaGetSymbolAddress((void**)&p_fbh, g_fbh);

    const int CORR_SMEM = 17408 + 33792 + 4096;   // 55296
    cudaFuncSetAttribute(corr_kernel, cudaFuncAttributeMaxDynamicSharedMemorySize, CORR_SMEM);
    cudaFuncSetAttribute(conv_kernel<10, 10>, cudaFuncAttributeMaxDynamicSharedMemorySize,
                         81 * 100 * (int)sizeof(float2));

    const int NS  = BATCH * S / 256;        // 10368
    const int NG6 = BATCH * (S / 6) / 256;  // 1728
    const int NG18 = BATCH * (S / 18) / 256; // 576
    const size_t NH4 = (size_t)BATCH * CH * P / 4;
    // order: corr is the 4th launch (profiler slot)
    zero_pool_kernel<<<NS, 256>>>();
    norm_kernel<<<BATCH * P / 256, 256>>>(fa, fb);
    scale_half_kernel<<<(unsigned)((NH4 + 255) / 256), 256>>>(fa, fb);
    corr_kernel<<<dim3(18, 9, 8), 256, CORR_SMEM>>>(p_fah, p_fbh);

    rowmax_kernel<<<BATCH * PI / 8, 256>>>(0);
    colmax_kernel<<<dim3(8, 16), PI>>>(0);
    mm_apply_kernel<<<NS, 256>>>(0, nullptr);

    conv_kernel<1, 10><<<NG6, 256, 81 * 10 * sizeof(float2)>>>(p_x0, p_y1, w1, b1);
    conv_kernel<10, 10><<<NG6, 256, 81 * 100 * sizeof(float2)>>>(p_y1, p_y2, w2, b2);
    conv3_kernel<<<NG18, 256>>>(p_y2, p_y3, w3, b3);

    zero_cmax_kernel<<<(BATCH * PI + 255) / 256, 256>>>();
    rowmax_kernel<<<BATCH * PI / 8, 256>>>(1);
    colmax_kernel<<<dim3(8, 16), PI>>>(1);
    mm_apply_kernel<<<NS, 256>>>(1, out);
}

// round 16
// speedup vs baseline: 1.1431x; 1.1431x over previous
#include <cuda_runtime.h>
#include <cuda_pipeline.h>
#include <cuda_fp16.h>
#include <mma.h>
#include <cstdint>

using namespace nvcuda;

namespace {
constexpr int BATCH = 8;
constexpr int CH    = 1024;
constexpr int P     = 48 * 48;     // 2304
constexpr int PD    = 24;
constexpr int PI    = PD * PD;     // 576
constexpr int S     = PI * PI;     // 331776
constexpr float EPS_L2 = 1e-6f;
constexpr float EPS_MM = 1e-5f;
}

__device__ float  g_inva[BATCH * P];
__device__ float  g_invb[BATCH * P];
__device__ __half g_fah[(size_t)BATCH * CH * P];  // scaled fp16 A, [b][k][p]
__device__ __half g_fbh[(size_t)BATCH * CH * P];  // scaled fp16 B, [b][k][p]
__device__ float  g_pool[(size_t)BATCH * S];
__device__ float  g_x0  [(size_t)BATCH * S];
__device__ float  g_y1  [(size_t)BATCH * 10 * S];
__device__ float  g_y2  [(size_t)BATCH * 10 * S];
__device__ float  g_y3  [(size_t)BATCH * S];
__device__ float  g_rmax[BATCH * PI];
__device__ float  g_cmax[BATCH * PI];

// ---------------- f32x2 packed helpers (convs) ----------------
__device__ __forceinline__ void fma2(unsigned long long& d, unsigned long long a,
                                     unsigned long long b) {
    asm("fma.rn.f32x2 %0, %1, %2, %0;" : "+l"(d) : "l"(a), "l"(b));
}
__device__ __forceinline__ unsigned long long pack2(float lo, float hi) {
    unsigned long long r;
    asm("mov.b64 %0, {%1, %2};" : "=l"(r) : "f"(lo), "f"(hi));
    return r;
}
__device__ __forceinline__ void unpack2(unsigned long long v, float& lo, float& hi) {
    asm("mov.b64 {%0, %1}, %2;" : "=f"(lo), "=f"(hi) : "l"(v));
}

// ---------------- per-position inverse L2 norms ----------------
__global__ void norm_kernel(const float* __restrict__ fa, const float* __restrict__ fb) {
    int idx = blockIdx.x * blockDim.x + threadIdx.x;
    int b = idx / P, p = idx - b * P;
    const float* a  = fa + (size_t)b * CH * P + p;
    const float* bb = fb + (size_t)b * CH * P + p;
    float sa = 0.f, sb = 0.f;
#pragma unroll 8
    for (int c = 0; c < CH; c++) {
        float x = a[(size_t)c * P];  sa = fmaf(x, x, sa);
        float y = bb[(size_t)c * P]; sb = fmaf(y, y, sb);
    }
    g_inva[idx] = rsqrtf(sa + EPS_L2);
    g_invb[idx] = rsqrtf(sb + EPS_L2);
}

__global__ void zero_pool_kernel() {
    size_t i = (size_t)blockIdx.x * blockDim.x + threadIdx.x;
    g_pool[i] = 0.f;
    if (i < BATCH * PI) g_cmax[i] = 0.f;
}
__global__ void zero_cmax_kernel() {
    int i = blockIdx.x * blockDim.x + threadIdx.x;
    if (i < BATCH * PI) g_cmax[i] = 0.f;
}

// ---- scale-by-invnorm + fp16 convert, layout preserved [b][k][p] ----
__global__ void scale_half_kernel(const float* __restrict__ fa,
                                  const float* __restrict__ fb) {
    size_t i4 = (size_t)blockIdx.x * blockDim.x + threadIdx.x;   // 4 elements each
    size_t i  = i4 * 4;
    if (i >= (size_t)BATCH * CH * P) return;
    int b  = (int)(i / ((size_t)CH * P));
    int p  = (int)(i % P);
    const float4 a4 = *reinterpret_cast<const float4*>(fa + i);
    const float4 b4 = *reinterpret_cast<const float4*>(fb + i);
    const float* ia = g_inva + b * P + p;
    const float* ib = g_invb + b * P + p;
    __half2 ha0 = __floats2half2_rn(a4.x * ia[0], a4.y * ia[1]);
    __half2 ha1 = __floats2half2_rn(a4.z * ia[2], a4.w * ia[3]);
    __half2 hb0 = __floats2half2_rn(b4.x * ib[0], b4.y * ib[1]);
    __half2 hb1 = __floats2half2_rn(b4.z * ib[2], b4.w * ib[3]);
    *reinterpret_cast<__half2*>(&g_fah[i])     = ha0;
    *reinterpret_cast<__half2*>(&g_fah[i + 2]) = ha1;
    *reinterpret_cast<__half2*>(&g_fbh[i])     = hb0;
    *reinterpret_cast<__half2*>(&g_fbh[i + 2]) = hb1;
}

// ---- correlation GEMM: fp16 wmma, fp16 ACC, BM=128 BN=256, 64x64 warps ----
// Frozen at R13 winner (470us, regs 126, no spills).
__global__ void __launch_bounds__(256, 2)
corr_kernel(const __half* __restrict__ fah, const __half* __restrict__ fbh) {
    extern __shared__ __align__(16) char sm[];
    __half* Asm = reinterpret_cast<__half*>(sm);            // [2][32][136]
    __half* Bsm = reinterpret_cast<__half*>(sm + 17408);    // [2][32][264]
    __half* wb  = reinterpret_cast<__half*>(sm + 17408 + 33792);  // [8][256]

    const int b  = blockIdx.z;
    const __half* Ag = fah + (size_t)b * CH * P;
    const __half* Bg = fbh + (size_t)b * CH * P;
    const int m0 = blockIdx.x * 128, n0 = blockIdx.y * 256;
    const int tid = threadIdx.x, wid = tid >> 5, lane = tid & 31;
    const int wm = wid & 1, wn = wid >> 1;   // warp tile 64(m) x 64(n)

    wmma::fragment<wmma::accumulator, 16, 16, 16, __half> acc[4][4];
#pragma unroll
    for (int i = 0; i < 4; i++)
#pragma unroll
        for (int j = 0; j < 4; j++) wmma::fill_fragment(acc[i][j], __float2half(0.f));

    auto As = [&](int buf, int r, int c) -> __half* { return Asm + (buf * 32 + r) * 136 + c; };
    auto Bs = [&](int buf, int r, int c) -> __half* { return Bsm + (buf * 32 + r) * 264 + c; };

    auto load_tile = [&](int kt, int buf) {
        const int k0 = kt * 32;
#pragma unroll
        for (int v = 0; v < 2; v++) {              // A: 128 wide
            int l = v * 256 + tid;
            int r = l >> 4, c = (l & 15) * 8;
            __pipeline_memcpy_async(As(buf, r, c), Ag + (size_t)(k0 + r) * P + m0 + c, 16);
        }
#pragma unroll
        for (int v = 0; v < 4; v++) {              // B: 256 wide
            int l = v * 256 + tid;
            int r = l >> 5, c = (l & 31) * 8;
            __pipeline_memcpy_async(Bs(buf, r, c), Bg + (size_t)(k0 + r) * P + n0 + c, 16);
        }
        __pipeline_commit();
    };

    load_tile(0, 0);
    const int NT = CH / 32;   // 32
    for (int kt = 0; kt < NT; kt++) {
        if (kt + 1 < NT) load_tile(kt + 1, (kt + 1) & 1);
        __pipeline_wait_prior((kt + 1 < NT) ? 1 : 0);
        __syncthreads();
        const int buf = kt & 1;
#pragma unroll
        for (int ks = 0; ks < 2; ks++) {
            const int kk = ks * 16;
            wmma::fragment<wmma::matrix_a, 16, 16, 16, __half, wmma::col_major> af[4];
#pragma unroll
            for (int i = 0; i < 4; i++)
                wmma::load_matrix_sync(af[i], As(buf, kk, wm * 64 + i * 16), 136);
#pragma unroll
            for (int j = 0; j < 4; j++) {
                wmma::fragment<wmma::matrix_b, 16, 16, 16, __half, wmma::row_major> bf;
                wmma::load_matrix_sync(bf, Bs(buf, kk, wn * 64 + j * 16), 264);
#pragma unroll
                for (int i = 0; i < 4; i++)
                    wmma::mma_sync(acc[i][j], af[i], bf, acc[i][j]);
            }
        }
        __syncthreads();
    }

    __half* wbuf = wb + wid * 256;
#pragma unroll 1
    for (int i = 0; i < 4; i++) {
#pragma unroll 1
        for (int j = 0; j < 4; j++) {
            wmma::store_matrix_sync(wbuf, acc[i][j], 16, wmma::mem_row_major);
            __syncwarp();
            const int tm0 = m0 + wm * 64 + i * 16;
            const int tn0 = n0 + wn * 64 + j * 16;
            const int row = lane >> 1;
            const int cb  = (lane & 1) * 8;
            const int p   = tm0 + row;
            float v[8];
#pragma unroll
            for (int c = 0; c < 8; c++) v[c] = __half2float(wbuf[row * 16 + cb + c]);
            float c2[4];
#pragma unroll
            for (int u = 0; u < 4; u++) c2[u] = fmaxf(v[2 * u], v[2 * u + 1]);
#pragma unroll
            for (int u = 0; u < 4; u++)
                c2[u] = fmaxf(c2[u], __shfl_xor_sync(0xffffffffu, c2[u], 2));
            if ((lane & 2) == 0) {
                const int PA = ((p / 48) >> 1) * 24 + ((p % 48) >> 1);
                float* poolb = g_pool + (size_t)b * S + (size_t)PA * PI;
#pragma unroll
                for (int u = 0; u < 4; u++) {
                    int q  = tn0 + cb + 2 * u;
                    int PB = ((q / 48) >> 1) * 24 + ((q % 48) >> 1);
                    atomicMax(reinterpret_cast<int*>(&poolb[PB]), __float_as_int(c2[u]));
                }
            }
            __syncwarp();
        }
    }
}

// ---------------- mutual matching ----------------
__global__ void rowmax_kernel(int which) {
    const float* x = (which == 0) ? g_pool : g_y3;
    int row  = blockIdx.x * 8 + (threadIdx.x >> 5);
    int lane = threadIdx.x & 31;
    const float* xr = x + (size_t)row * PI;
    float m = 0.f;
    for (int j = lane; j < PI; j += 32) m = fmaxf(m, xr[j]);
#pragma unroll
    for (int o = 16; o; o >>= 1) m = fmaxf(m, __shfl_xor_sync(0xffffffffu, m, o));
    if (lane == 0) g_rmax[row] = m;
}

__global__ void colmax_kernel(int which) {  // grid (8,16), 576 thr
    const float* x = (which == 0) ? g_pool : g_y3;
    int b = blockIdx.x, j = threadIdx.x;
    const float* xb = x + (size_t)b * S;
    int i0 = blockIdx.y * 36;
    float m = 0.f;
    for (int i = i0; i < i0 + 36; i++) m = fmaxf(m, xb[(size_t)i * PI + j]);
    atomicMax(reinterpret_cast<int*>(&g_cmax[b * PI + j]), __float_as_int(m));
}

__global__ void mm_apply_kernel(int which, float* __restrict__ outp) {
    int idx = blockIdx.x * blockDim.x + threadIdx.x;
    int b = idx / S, rem = idx - b * S;
    int i = rem / PI, j = rem - i * PI;
    float v  = which ? g_y3[idx] : g_pool[idx];
    float rm = g_rmax[b * PI + i];
    float cm = g_cmax[b * PI + j];
    if (which == 0) {  // deferred x/sqrt(x^2+eps); monotone so maxes transform too
        v  = v  * rsqrtf(v  * v  + EPS_L2);
        rm = rm * rsqrtf(rm * rm + EPS_L2);
        cm = cm * rsqrtf(cm * cm + EPS_L2);
    }
    float* dst = which ? outp : g_x0;
    dst[idx] = v * (v / (rm + EPS_MM)) * (v / (cm + EPS_MM));
}

// ---- Conv4d 3^4 SAME: f32x2 FMA, 6 outputs/thread (R13 exact, for conv2) ----
template <int CI, int CO>
__global__ void __launch_bounds__(256)
conv_kernel(const float* __restrict__ x, float* __restrict__ y,
            const float* __restrict__ w, const float* __restrict__ bias) {
    extern __shared__ __align__(16) char dsm[];
    float2* ws2 = reinterpret_cast<float2*>(dsm);  // duplicated weight pairs
    __shared__ float bs[CO];
    for (int l = threadIdx.x; l < 81 * CI * CO; l += 256) {
        int tap = l / (CI * CO), r = l - tap * (CI * CO);
        int ci = r / CO, co = r - ci * CO;
        float wv = w[(co * CI + ci) * 81 + tap];
        ws2[l] = make_float2(wv, wv);
    }
    if (threadIdx.x < CO) bs[threadIdx.x] = bias[threadIdx.x];
    __syncthreads();

    int g = blockIdx.x * 256 + threadIdx.x;           // [0, BATCH*S/6)
    int b = g / (S / 6), r = g - b * (S / 6);
    int d4b = (r & 3) * 6; int r2 = r >> 2;
    int d3 = r2 % 24; r2 /= 24;
    int d2 = r2 % 24; int d1 = r2 / 24;
    int s0 = ((d1 * 24 + d2) * 24 + d3) * 24 + d4b;
    const bool leftEdge = (d4b == 0), rightEdge = (d4b == 18);
    const float* xb = x + (size_t)b * CI * S;

    unsigned long long acc[3][CO];
#pragma unroll
    for (int h = 0; h < 3; h++)
#pragma unroll
        for (int co = 0; co < CO; co++) acc[h][co] = 0ull;

#pragma unroll 1
    for (int t1 = 0; t1 < 3; t1++) {
        int e1 = d1 + t1 - 1; if ((unsigned)e1 >= 24u) continue;
#pragma unroll 1
        for (int t2 = 0; t2 < 3; t2++) {
            int e2 = d2 + t2 - 1; if ((unsigned)e2 >= 24u) continue;
#pragma unroll 1
            for (int t3 = 0; t3 < 3; t3++) {
                int e3 = d3 + t3 - 1; if ((unsigned)e3 >= 24u) continue;
                int spb  = ((e1 * 24 + e2) * 24 + e3) * 24 + d4b;
                int tap3 = ((t1 * 3 + t2) * 3 + t3) * 3;
#pragma unroll
                for (int ci = 0; ci < CI; ci++) {
                    const float* xr = xb + (size_t)ci * S + spb;   // = w1
                    const float2* xp = reinterpret_cast<const float2*>(xr);
                    float2 m0 = xp[0], m1 = xp[1], m2 = xp[2];     // w1..w6
                    float wL = leftEdge  ? 0.f : xr[-1];           // w0
                    float wR = rightEdge ? 0.f : xr[6];            // w7
                    unsigned long long E0 = pack2(wL,   m0.x);
                    unsigned long long E1 = pack2(m0.y, m1.x);
                    unsigned long long E2 = pack2(m1.y, m2.x);
                    unsigned long long E3 = pack2(m2.y, wR);
                    unsigned long long O0 = pack2(m0.x, m0.y);
                    unsigned long long O1 = pack2(m1.x, m1.y);
                    unsigned long long O2 = pack2(m2.x, m2.y);
                    const unsigned long long T[3][3] = {
                        {E0, E1, E2}, {O0, O1, O2}, {E1, E2, E3} };
#pragma unroll
                    for (int t4 = 0; t4 < 3; t4++) {
                        const unsigned long long A = T[t4][0], Bp = T[t4][1], Cp = T[t4][2];
                        const float2* wrow = ws2 + ((tap3 + t4) * CI + ci) * CO;
                        if (CO % 2 == 0) {
                            const ulonglong2* wq2 = reinterpret_cast<const ulonglong2*>(wrow);
#pragma unroll
                            for (int c2 = 0; c2 < CO / 2; c2++) {
                                ulonglong2 wv = wq2[c2];
                                fma2(acc[0][2 * c2],     A,  wv.x);
                                fma2(acc[1][2 * c2],     Bp, wv.x);
                                fma2(acc[2][2 * c2],     Cp, wv.x);
                                fma2(acc[0][2 * c2 + 1], A,  wv.y);
                                fma2(acc[1][2 * c2 + 1], Bp, wv.y);
                                fma2(acc[2][2 * c2 + 1], Cp, wv.y);
                            }
                        } else {
                            const unsigned long long* wq =
                                reinterpret_cast<const unsigned long long*>(wrow);
#pragma unroll
                            for (int co = 0; co < CO; co++) {
                                unsigned long long wv = wq[co];
                                fma2(acc[0][co], A,  wv);
                                fma2(acc[1][co], Bp, wv);
                                fma2(acc[2][co], Cp, wv);
                            }
                        }
                    }
                }
            }
        }
    }
#pragma unroll
    for (int co = 0; co < CO; co++) {
        float bb = bs[co];
        float* yo = &y[((size_t)b * CO + co) * S + s0];
#pragma unroll
        for (int h = 0; h < 3; h++) {
            float a0, a1;
            unpack2(acc[h][co], a0, a1);
            float2 o = make_float2(fmaxf(a0 + bb, 0.f), fmaxf(a1 + bb, 0.f));
            *reinterpret_cast<float2*>(yo + 2 * h) = o;
        }
    }
}

// ---- conv1 specialized (CI=1, CO=10): batched 3-row loads (MLP 5->15) ----
// CI=1 keeps regs ~104 under the (256,2) cap — no spill (unlike the R14
// CI=10 variant). Edge rows zero-filled; 0*w adds exactly 0.
__global__ void __launch_bounds__(256, 2)
conv1_kernel(const float* __restrict__ x, float* __restrict__ y,
             const float* __restrict__ w, const float* __restrict__ bias) {
    __shared__ unsigned long long ws2[810];   // [tap*10+co] duplicated pairs
    __shared__ float bs[10];
    for (int l = threadIdx.x; l < 810; l += 256) {
        int tap = l / 10, co = l - tap * 10;
        float wv = w[co * 81 + tap];
        ws2[l] = pack2(wv, wv);
    }
    if (threadIdx.x < 10) bs[threadIdx.x] = bias[threadIdx.x];
    __syncthreads();

    int g = blockIdx.x * 256 + threadIdx.x;           // [0, BATCH*S/6)
    int b = g / (S / 6), r = g - b * (S / 6);
    int d4b = (r & 3) * 6; int r2 = r >> 2;
    int d3 = r2 % 24; r2 /= 24;
    int d2 = r2 % 24; int d1 = r2 / 24;
    int s0 = ((d1 * 24 + d2) * 24 + d3) * 24 + d4b;
    const bool leftEdge = (d4b == 0), rightEdge = (d4b == 18);
    const float* xb = x + (size_t)b * S;

    unsigned long long acc[3][10];
#pragma unroll
    for (int h = 0; h < 3; h++)
#pragma unroll
        for (int co = 0; co < 10; co++) acc[h][co] = 0ull;

#pragma unroll 1
    for (int t1 = 0; t1 < 3; t1++) {
        int e1 = d1 + t1 - 1; if ((unsigned)e1 >= 24u) continue;
#pragma unroll 1
        for (int t2 = 0; t2 < 3; t2++) {
            int e2 = d2 + t2 - 1; if ((unsigned)e2 >= 24u) continue;
            int plane = (e1 * 24 + e2) * 24;
            int tap2  = (t1 * 3 + t2) * 9;
            float rw[3][8];
#pragma unroll
            for (int rr = 0; rr < 3; rr++) {
                int e3 = d3 + rr - 1;
                bool valid = (unsigned)e3 < 24u;
                const float* xr = xb + (plane + (valid ? e3 : 0)) * 24 + d4b;
                const float2* xp = reinterpret_cast<const float2*>(xr);
                float2 a0 = valid ? xp[0] : make_float2(0.f, 0.f);
                float2 a1 = valid ? xp[1] : make_float2(0.f, 0.f);
                float2 a2 = valid ? xp[2] : make_float2(0.f, 0.f);
                rw[rr][0] = (valid && !leftEdge)  ? xr[-1] : 0.f;
                rw[rr][7] = (valid && !rightEdge) ? xr[6]  : 0.f;
                rw[rr][1] = a0.x; rw[rr][2] = a0.y;
                rw[rr][3] = a1.x; rw[rr][4] = a1.y;
                rw[rr][5] = a2.x; rw[rr][6] = a2.y;
            }
#pragma unroll
            for (int t3 = 0; t3 < 3; t3++) {
                const float* q = rw[t3];
                unsigned long long E0 = pack2(q[0], q[1]);
                unsigned long long E1 = pack2(q[2], q[3]);
                unsigned long long E2 = pack2(q[4], q[5]);
                unsigned long long E3 = pack2(q[6], q[7]);
                unsigned long long O0 = pack2(q[1], q[2]);
                unsigned long long O1 = pack2(q[3], q[4]);
                unsigned long long O2 = pack2(q[5], q[6]);
                const unsigned long long T[3][3] = {
                    {E0, E1, E2}, {O0, O1, O2}, {E1, E2, E3} };
#pragma unroll
                for (int t4 = 0; t4 < 3; t4++) {
                    const unsigned long long A = T[t4][0], Bp = T[t4][1], Cp = T[t4][2];
                    const unsigned long long* wq = &ws2[(tap2 + t3 * 3 + t4) * 10];
#pragma unroll
                    for (int co = 0; co < 10; co++) {
                        unsigned long long wv = wq[co];
                        fma2(acc[0][co], A,  wv);
                        fma2(acc[1][co], Bp, wv);
                        fma2(acc[2][co], Cp, wv);
                    }
                }
            }
        }
    }
#pragma unroll
    for (int co = 0; co < 10; co++) {
        float bb = bs[co];
        float* yo = &y[((size_t)b * 10 + co) * S + s0];
#pragma unroll
        for (int h = 0; h < 3; h++) {
            float a0, a1;
            unpack2(acc[h][co], a0, a1);
            *reinterpret_cast<float2*>(yo + 2 * h) =
                make_float2(fmaxf(a0 + bb, 0.f), fmaxf(a1 + bb, 0.f));
        }
    }
}

// ---- conv3 specialized (CI=10, CO=1): 18 outputs/thread (R13 exact) ----
__global__ void __launch_bounds__(256)
conv3_kernel(const float* __restrict__ x, float* __restrict__ y,
             const float* __restrict__ w, const float* __restrict__ bias) {
    __shared__ unsigned long long ws2[810];   // duplicated weight pairs [tap*10+ci]
    __shared__ float bs0;
    for (int l = threadIdx.x; l < 810; l += 256) {
        int tap = l / 10, ci = l - tap * 10;
        float wv = w[ci * 81 + tap];
        ws2[l] = pack2(wv, wv);
    }
    if (threadIdx.x == 0) bs0 = bias[0];
    __syncthreads();

    int g = blockIdx.x * 256 + threadIdx.x;   // [0, BATCH*S/18)
    int b = g / (S / 18), r = g - b * (S / 18);
    int d4b = (r & 3) * 6; int r2 = r >> 2;
    int d3s = (r2 & 7) * 3; r2 >>= 3;
    int d2 = r2 % 24; int d1 = r2 / 24;
    const bool leftEdge = (d4b == 0), rightEdge = (d4b == 18);
    const float* xb = x + (size_t)b * 10 * S;

    unsigned long long acc[3][3];
#pragma unroll
    for (int o = 0; o < 3; o++)
#pragma unroll
        for (int h = 0; h < 3; h++) acc[o][h] = 0ull;

#pragma unroll 1
    for (int t1 = 0; t1 < 3; t1++) {
        int e1 = d1 + t1 - 1; if ((unsigned)e1 >= 24u) continue;
#pragma unroll 1
        for (int t2 = 0; t2 < 3; t2++) {
            int e2 = d2 + t2 - 1; if ((unsigned)e2 >= 24u) continue;
            int plane = (e1 * 24 + e2) * 24;
            int tap2  = (t1 * 3 + t2) * 9;
#pragma unroll 1
            for (int ci = 0; ci < 10; ci++) {
                const float* xc = xb + (size_t)ci * S;
#pragma unroll
                for (int j = 0; j < 5; j++) {
                    int e3 = d3s - 1 + j;
                    if ((unsigned)e3 >= 24u) continue;
                    const float* xr = xc + (plane + e3) * 24 + d4b;
                    const float2* xp = reinterpret_cast<const float2*>(xr);
                    float2 m0 = xp[0], m1 = xp[1], m2 = xp[2];
                    float wL = leftEdge  ? 0.f : xr[-1];
                    float wR = rightEdge ? 0.f : xr[6];
                    unsigned long long E0 = pack2(wL,   m0.x);
                    unsigned long long E1 = pack2(m0.y, m1.x);
                    unsigned long long E2 = pack2(m1.y, m2.x);
                    unsigned long long E3 = pack2(m2.y, wR);
                    unsigned long long O0 = pack2(m0.x, m0.y);
                    unsigned long long O1 = pack2(m1.x, m1.y);
                    unsigned long long O2 = pack2(m2.x, m2.y);
                    const unsigned long long T[3][3] = {
                        {E0, E1, E2}, {O0, O1, O2}, {E1, E2, E3} };
#pragma unroll
                    for (int t3 = 0; t3 < 3; t3++) {
                        int o = j - t3;
                        if ((unsigned)o >= 3u) continue;
                        const unsigned long long* wq = &ws2[(tap2 + t3 * 3) * 10 + ci];
#pragma unroll
                        for (int t4 = 0; t4 < 3; t4++) {
                            unsigned long long wv = wq[t4 * 10];
                            fma2(acc[o][0], T[t4][0], wv);
                            fma2(acc[o][1], T[t4][1], wv);
                            fma2(acc[o][2], T[t4][2], wv);
                        }
                    }
                }
            }
        }
    }
    float bb = bs0;
#pragma unroll
    for (int o = 0; o < 3; o++) {
        float* yo = &y[(size_t)b * S + ((d1 * 24 + d2) * 24 + d3s + o) * 24 + d4b];
#pragma unroll
        for (int h = 0; h < 3; h++) {
            float a0, a1;
            unpack2(acc[o][h], a0, a1);
            *reinterpret_cast<float2*>(yo + 2 * h) =
                make_float2(fmaxf(a0 + bb, 0.f), fmaxf(a1 + bb, 0.f));
        }
    }
}

extern "C" void kernel_launch(void* const* d_in, const int* in_sizes, int n_in,
                              void* d_out, int out_size) {
    const float* fa = (const float*)d_in[0];
    const float* fb = (const float*)d_in[1];
    const float* w1 = (const float*)d_in[2];
    const float* b1 = (const float*)d_in[3];
    const float* w2 = (const float*)d_in[4];
    const float* b2 = (const float*)d_in[5];
    const float* w3 = (const float*)d_in[6];
    const float* b3 = (const float*)d_in[7];
    float* out = (float*)d_out;

    float *p_x0, *p_y1, *p_y2, *p_y3;
    __half *p_fah, *p_fbh;
    cudaGetSymbolAddress((void**)&p_x0, g_x0);
    cudaGetSymbolAddress((void**)&p_y1, g_y1);
    cudaGetSymbolAddress((void**)&p_y2, g_y2);
    cudaGetSymbolAddress((void**)&p_y3, g_y3);
    cudaGetSymbolAddress((void**)&p_fah, g_fah);
    cudaGetSymbolAddress((void**)&p_fbh, g_fbh);

    const int CORR_SMEM = 17408 + 33792 + 4096;   // 55296
    cudaFuncSetAttribute(corr_kernel, cudaFuncAttributeMaxDynamicSharedMemorySize, CORR_SMEM);
    cudaFuncSetAttribute(conv_kernel<10, 10>, cudaFuncAttributeMaxDynamicSharedMemorySize,
                         81 * 100 * (int)sizeof(float2));

    const int NS  = BATCH * S / 256;        // 10368
    const int NG6 = BATCH * (S / 6) / 256;  // 1728
    const int NG18 = BATCH * (S / 18) / 256; // 576
    const size_t NH4 = (size_t)BATCH * CH * P / 4;
    // order: corr is the 4th launch (profiler slot)
    zero_pool_kernel<<<NS, 256>>>();
    norm_kernel<<<BATCH * P / 256, 256>>>(fa, fb);
    scale_half_kernel<<<(unsigned)((NH4 + 255) / 256), 256>>>(fa, fb);
    corr_kernel<<<dim3(18, 9, 8), 256, CORR_SMEM>>>(p_fah, p_fbh);

    rowmax_kernel<<<BATCH * PI / 8, 256>>>(0);
    colmax_kernel<<<dim3(8, 16), PI>>>(0);
    mm_apply_kernel<<<NS, 256>>>(0, nullptr);

    conv1_kernel<<<NG6, 256>>>(p_x0, p_y1, w1, b1);
    conv_kernel<10, 10><<<NG6, 256, 81 * 100 * sizeof(float2)>>>(p_y1, p_y2, w2, b2);
    conv3_kernel<<<NG18, 256>>>(p_y2, p_y3, w3, b3);

    zero_cmax_kernel<<<(BATCH * PI + 255) / 256, 256>>>();
    rowmax_kernel<<<BATCH * PI / 8, 256>>>(1);
    colmax_kernel<<<dim3(8, 16), PI>>>(1);
    mm_apply_kernel<<<NS, 256>>>(1, out);
}